// round 6
// baseline (speedup 1.0000x reference)
#include <cuda_runtime.h>
#include <math.h>
#include <stdint.h>

#define L 2048
#define Bb 2
#define Dd 1024
#define Hh 16
#define SPAN 128
#define LN_EPS 1e-5f

#define MROWS (L * Bb)                          // 4096
#define LBD ((size_t)L * Bb * Dd)               // 4,194,304
#define ATTN_ELEMS ((size_t)Hh * Bb * L * L)    // 134,217,728

// ---------------- scratch ----------------
__device__ float g_q [Hh * Bb * L * 64];    // [h][b][l][k]  natural
__device__ float g_k [Hh * Bb * L * 64];    // [h][b][l][k]  natural
__device__ float g_vT[Hh * Bb * 64 * L];    // [h][b][v][l]  transposed
__device__ float g_ctx[MROWS * Dd];
__device__ float g_yp [MROWS * Dd];

// ---------------- helpers ----------------
__device__ __forceinline__ unsigned f2tf32(float x) {
    unsigned u;
    asm("cvt.rna.tf32.f32 %0, %1;" : "=r"(u) : "f"(x));
    return u;
}
__device__ __forceinline__ float rnaf(float x) { return __uint_as_float(f2tf32(x)); }

__device__ __forceinline__ void mma_tf32(float c[4],
                                         unsigned a0, unsigned a1, unsigned a2, unsigned a3,
                                         unsigned b0, unsigned b1) {
    asm volatile(
        "mma.sync.aligned.m16n8k8.row.col.f32.tf32.tf32.f32 "
        "{%0,%1,%2,%3},{%4,%5,%6,%7},{%8,%9},{%0,%1,%2,%3};"
        : "+f"(c[0]), "+f"(c[1]), "+f"(c[2]), "+f"(c[3])
        : "r"(a0), "r"(a1), "r"(a2), "r"(a3), "r"(b0), "r"(b1));
}
#define U(x) __float_as_uint(x)

// ---------------- TF32 tensor-core GEMM: 128x128x32 tiles ----------------
// A smem: [m][k'] with k' = (k&3)*8 + (k>>2)  -> vectorized fragment loads
// B smem: [k][n]  (scalar frag loads, conflict-free)
// MODE 0: natural permute  out[((h*2+b)*L + l)*64 + k]   (Q, K)
// MODE 2: transposed       out[((h*2+b)*64 + k)*L + l]   (V)
// MODE 1: FC               out = acc + bias + resid
#define AS_STRIDE 36
#define BS_STRIDE 136
#define GEMM_BUF (128 * AS_STRIDE + 32 * BS_STRIDE)
#define GEMM_SMEM_BYTES (2 * GEMM_BUF * 4)

template <int MODE>
__global__ __launch_bounds__(256) void mma_gemm(
    const float* __restrict__ A, const float* __restrict__ B,
    const float* __restrict__ bias, const float* __restrict__ resid,
    float* __restrict__ out)
{
    const int K = 1024, N = 1024;
    extern __shared__ float sm[];

    const int tid = threadIdx.x;
    const int lane = tid & 31;
    const int warp = tid >> 5;
    const int wm = warp >> 2;
    const int wn = warp & 3;
    const int qr = lane >> 2;
    const int ql = lane & 3;
    const int bm = blockIdx.y * 128;
    const int bn = blockIdx.x * 128;

    const int ar = tid >> 3;          // A row 0..31 (+32 steps)
    const int ak = (tid & 7) * 4;     // A col k, float4
    const int br = tid >> 5;          // B row k 0..7 (+8 steps)
    const int bc = (tid & 31) * 4;    // B col n, float4

    float acc[4][4][4];
#pragma unroll
    for (int i = 0; i < 4; i++)
#pragma unroll
        for (int j = 0; j < 4; j++)
#pragma unroll
            for (int e = 0; e < 4; e++) acc[i][j][e] = 0.f;

    float4 pa[4], pb[4];

    auto gload = [&](int kt) {
#pragma unroll
        for (int i = 0; i < 4; i++)
            pa[i] = *(const float4*)(A + (size_t)(bm + ar + 32 * i) * K + kt * 32 + ak);
#pragma unroll
        for (int i = 0; i < 4; i++)
            pb[i] = *(const float4*)(B + (size_t)(kt * 32 + br + 8 * i) * N + bn + bc);
    };
    auto sstore = [&](int buf) {
        float* As = sm + buf * GEMM_BUF;
        float* Bs = As + 128 * AS_STRIDE;
        const int t4 = ak >> 2;   // k>>2 for this float4 (k&3 = component index)
#pragma unroll
        for (int i = 0; i < 4; i++) {
            float* row = &As[(ar + 32 * i) * AS_STRIDE];
            row[0 * 8 + t4]  = __uint_as_float(f2tf32(pa[i].x));
            row[1 * 8 + t4]  = __uint_as_float(f2tf32(pa[i].y));
            row[2 * 8 + t4]  = __uint_as_float(f2tf32(pa[i].z));
            row[3 * 8 + t4]  = __uint_as_float(f2tf32(pa[i].w));
        }
#pragma unroll
        for (int i = 0; i < 4; i++) {
            float4 w;
            w.x = __uint_as_float(f2tf32(pb[i].x));
            w.y = __uint_as_float(f2tf32(pb[i].y));
            w.z = __uint_as_float(f2tf32(pb[i].z));
            w.w = __uint_as_float(f2tf32(pb[i].w));
            *(float4*)&Bs[(br + 8 * i) * BS_STRIDE + bc] = w;
        }
    };

    gload(0);
    sstore(0);
    __syncthreads();

    for (int kt = 0; kt < 32; kt++) {
        const int cur = kt & 1;
        if (kt < 31) gload(kt + 1);

        const float* As = sm + cur * GEMM_BUF;
        const float* Bs = As + 128 * AS_STRIDE;
#pragma unroll
        for (int u = 0; u < 2; u++) {
            float4 A0[4], A1[4];
#pragma unroll
            for (int mt = 0; mt < 4; mt++) {
                const int r = wm * 64 + mt * 16 + qr;
                A0[mt] = *(const float4*)&As[r * AS_STRIDE + ql * 8 + 4 * u];
                A1[mt] = *(const float4*)&As[(r + 8) * AS_STRIDE + ql * 8 + 4 * u];
            }
            unsigned bf[4][4];
#pragma unroll
            for (int nt = 0; nt < 4; nt++) {
                const int cc = wn * 32 + nt * 8 + qr;
                bf[nt][0] = U(Bs[(16 * u + ql) * BS_STRIDE + cc]);
                bf[nt][1] = U(Bs[(16 * u + ql + 4) * BS_STRIDE + cc]);
                bf[nt][2] = U(Bs[(16 * u + 8 + ql) * BS_STRIDE + cc]);
                bf[nt][3] = U(Bs[(16 * u + 8 + ql + 4) * BS_STRIDE + cc]);
            }
#pragma unroll
            for (int mt = 0; mt < 4; mt++)
#pragma unroll
                for (int nt = 0; nt < 4; nt++)
                    mma_tf32(acc[mt][nt], U(A0[mt].x), U(A1[mt].x), U(A0[mt].y), U(A1[mt].y),
                             bf[nt][0], bf[nt][1]);
#pragma unroll
            for (int mt = 0; mt < 4; mt++)
#pragma unroll
                for (int nt = 0; nt < 4; nt++)
                    mma_tf32(acc[mt][nt], U(A0[mt].z), U(A1[mt].z), U(A0[mt].w), U(A1[mt].w),
                             bf[nt][2], bf[nt][3]);
        }

        if (kt < 31) {
            sstore(1 - cur);
            __syncthreads();
        }
    }

#pragma unroll
    for (int mt = 0; mt < 4; mt++) {
#pragma unroll
        for (int nt = 0; nt < 4; nt++) {
            const int row0 = bm + wm * 64 + mt * 16 + (lane >> 2);
            const int col0 = bn + wn * 32 + nt * 8 + (lane & 3) * 2;
#pragma unroll
            for (int half = 0; half < 2; half++) {
                const int m = row0 + half * 8;
#pragma unroll
                for (int e = 0; e < 2; e++) {
                    const int n = col0 + e;
                    float val = acc[mt][nt][half * 2 + e] + bias[n];
                    if (MODE == 0) {
                        const int l = m >> 1, b = m & 1, h = n >> 6, k = n & 63;
                        out[(((size_t)(h * Bb + b) * L + l) * 64) + k] = val;
                    } else if (MODE == 2) {
                        const int l = m >> 1, b = m & 1, h = n >> 6, k = n & 63;
                        out[(((size_t)(h * Bb + b) * 64 + k) * L) + l] = val;
                    } else {
                        val += resid[(size_t)m * N + n];
                        out[(size_t)m * N + n] = val;
                    }
                }
            }
        }
    }
}

// ---------------- banded attention via mma.sync tf32, split hoisted to smem ----------------
// k-permuted smem layout: k' = (k&3)*16 + (k>>2), stride 68.
// Phase 1 tiles: Qhi, Qlo, Khi, Klo. Phase 2 reuses: P(=Qhi slot), V(=Khi slot).
#define ATS 68
#define ATTN_SMEM_BYTES (4 * 64 * ATS * 4)

__global__ __launch_bounds__(256, 2) void attn_mma(float* __restrict__ attn_out,
                                                   int write_attn)
{
    extern __shared__ float sbuf[];
    float* Qhi = sbuf;                 // phase2: P
    float* Qlo = sbuf + 64 * ATS;
    float* Khi = sbuf + 2 * 64 * ATS;  // phase2: V
    float* Klo = sbuf + 3 * 64 * ATS;
    __shared__ float Rm[2][64], Rs[2][64];

    const int tid = threadIdx.x;
    const int lane = tid & 31;
    const int wid = tid >> 5;
    const int wm = wid & 3;
    const int wn = wid >> 2;
    const int qr = lane >> 2;
    const int ql = lane & 3;
    const int h = blockIdx.z;
    const int b = blockIdx.y;
    const int hb = h * Bb + b;
    const int i0 = blockIdx.x * 64;
    const int iLo = i0 + wm * 16, iHi = iLo + 15;

    const float* qb  = g_q  + (size_t)hb * L * 64;
    const float* kb  = g_k  + (size_t)hb * L * 64;
    const float* vTb = g_vT + (size_t)hb * 64 * L;

    const int lr = tid >> 2;           // loader row 0..63
    const int lc0 = (tid & 3) * 4;     // loader col base

    // load Q tile, split hi/lo into permuted layout
    {
#pragma unroll
        for (int it = 0; it < 4; it++) {
            const int c = lc0 + it * 16;
            float4 x = *(const float4*)(qb + (size_t)(i0 + lr) * 64 + c);
            float* dh = &Qhi[lr * ATS + (c >> 2)];
            float* dl = &Qlo[lr * ATS + (c >> 2)];
            float h0 = rnaf(x.x); dh[0]  = h0; dl[0]  = rnaf(x.x - h0);
            float h1 = rnaf(x.y); dh[16] = h1; dl[16] = rnaf(x.y - h1);
            float h2 = rnaf(x.z); dh[32] = h2; dl[32] = rnaf(x.z - h2);
            float h3 = rnaf(x.w); dh[48] = h3; dl[48] = rnaf(x.w - h3);
        }
    }

    float s[5][4][4];
#pragma unroll
    for (int t = 0; t < 5; t++)
#pragma unroll
        for (int nt = 0; nt < 4; nt++)
#pragma unroll
            for (int e = 0; e < 4; e++) s[t][nt][e] = 0.f;

    // ---------- phase 1: scores ----------
#pragma unroll
    for (int t = 0; t < 5; t++) {
        const int j0 = i0 - SPAN + t * 64;
        if (j0 < 0 || j0 >= L) continue;

        __syncthreads();
        {
#pragma unroll
            for (int it = 0; it < 4; it++) {
                const int c = lc0 + it * 16;
                float4 x = *(const float4*)(kb + (size_t)(j0 + lr) * 64 + c);
                float* dh = &Khi[lr * ATS + (c >> 2)];
                float* dl = &Klo[lr * ATS + (c >> 2)];
                float h0 = rnaf(x.x); dh[0]  = h0; dl[0]  = rnaf(x.x - h0);
                float h1 = rnaf(x.y); dh[16] = h1; dl[16] = rnaf(x.y - h1);
                float h2 = rnaf(x.z); dh[32] = h2; dl[32] = rnaf(x.z - h2);
                float h3 = rnaf(x.w); dh[48] = h3; dl[48] = rnaf(x.w - h3);
            }
        }
        __syncthreads();

        bool ok[4];
#pragma unroll
        for (int nt = 0; nt < 4; nt++) {
            const int jlo = j0 + wn * 32 + nt * 8;
            ok[nt] = !((jlo + 7 < iLo - SPAN) || (jlo > iHi + SPAN));
        }

#pragma unroll
        for (int u = 0; u < 4; u++) {
            const int qa = (wm * 16 + qr) * ATS + ql * 16 + 4 * u;
            float4 h0 = *(const float4*)&Qhi[qa];
            float4 h1 = *(const float4*)&Qhi[qa + 8 * ATS];
            float4 l0 = *(const float4*)&Qlo[qa];
            float4 l1 = *(const float4*)&Qlo[qa + 8 * ATS];
#pragma unroll
            for (int nt = 0; nt < 4; nt++) {
                if (!ok[nt]) continue;
                const int ka = (wn * 32 + nt * 8 + qr) * ATS + ql * 16 + 4 * u;
                float4 bh = *(const float4*)&Khi[ka];
                float4 bl = *(const float4*)&Klo[ka];
                // k8 = 2u
                mma_tf32(s[t][nt], U(h0.x), U(h1.x), U(h0.y), U(h1.y), U(bh.x), U(bh.y));
                mma_tf32(s[t][nt], U(l0.x), U(l1.x), U(l0.y), U(l1.y), U(bh.x), U(bh.y));
                mma_tf32(s[t][nt], U(h0.x), U(h1.x), U(h0.y), U(h1.y), U(bl.x), U(bl.y));
                // k8 = 2u+1
                mma_tf32(s[t][nt], U(h0.z), U(h1.z), U(h0.w), U(h1.w), U(bh.z), U(bh.w));
                mma_tf32(s[t][nt], U(l0.z), U(l1.z), U(l0.w), U(l1.w), U(bh.z), U(bh.w));
                mma_tf32(s[t][nt], U(h0.z), U(h1.z), U(h0.w), U(h1.w), U(bl.z), U(bl.w));
            }
        }
    }

    // scale + band mask
#pragma unroll
    for (int t = 0; t < 5; t++) {
        const int j0 = i0 - SPAN + t * 64;
#pragma unroll
        for (int nt = 0; nt < 4; nt++)
#pragma unroll
            for (int e = 0; e < 4; e++) {
                const int i = i0 + wm * 16 + qr + ((e >= 2) ? 8 : 0);
                const int j = j0 + wn * 32 + nt * 8 + 2 * ql + (e & 1);
                const int d = j - i;
                const bool valid = (j >= 0) && (j < L) && (d >= -SPAN) && (d <= SPAN);
                s[t][nt][e] = valid ? s[t][nt][e] * 0.125f : -1e30f;
            }
    }

    // ---------- softmax ----------
    const int rlo = wm * 16 + qr, rhi = rlo + 8;
    float mlo = -1e30f, mhi = -1e30f;
#pragma unroll
    for (int t = 0; t < 5; t++)
#pragma unroll
        for (int nt = 0; nt < 4; nt++) {
            mlo = fmaxf(mlo, fmaxf(s[t][nt][0], s[t][nt][1]));
            mhi = fmaxf(mhi, fmaxf(s[t][nt][2], s[t][nt][3]));
        }
    mlo = fmaxf(mlo, __shfl_xor_sync(~0u, mlo, 1));
    mlo = fmaxf(mlo, __shfl_xor_sync(~0u, mlo, 2));
    mhi = fmaxf(mhi, __shfl_xor_sync(~0u, mhi, 1));
    mhi = fmaxf(mhi, __shfl_xor_sync(~0u, mhi, 2));
    if (ql == 0) { Rm[wn][rlo] = mlo; Rm[wn][rhi] = mhi; }
    __syncthreads();
    mlo = fmaxf(Rm[0][rlo], Rm[1][rlo]);
    mhi = fmaxf(Rm[0][rhi], Rm[1][rhi]);

    float slo = 0.f, shi = 0.f;
#pragma unroll
    for (int t = 0; t < 5; t++)
#pragma unroll
        for (int nt = 0; nt < 4; nt++) {
            s[t][nt][0] = __expf(s[t][nt][0] - mlo);
            s[t][nt][1] = __expf(s[t][nt][1] - mlo);
            s[t][nt][2] = __expf(s[t][nt][2] - mhi);
            s[t][nt][3] = __expf(s[t][nt][3] - mhi);
            slo += s[t][nt][0] + s[t][nt][1];
            shi += s[t][nt][2] + s[t][nt][3];
        }
    slo += __shfl_xor_sync(~0u, slo, 1);
    slo += __shfl_xor_sync(~0u, slo, 2);
    shi += __shfl_xor_sync(~0u, shi, 1);
    shi += __shfl_xor_sync(~0u, shi, 2);
    if (ql == 0) { Rs[wn][rlo] = slo; Rs[wn][rhi] = shi; }
    __syncthreads();
    const float invlo = 1.0f / (Rs[0][rlo] + Rs[1][rlo]);
    const float invhi = 1.0f / (Rs[0][rhi] + Rs[1][rhi]);
#pragma unroll
    for (int t = 0; t < 5; t++)
#pragma unroll
        for (int nt = 0; nt < 4; nt++) {
            s[t][nt][0] *= invlo;
            s[t][nt][1] *= invlo;
            s[t][nt][2] *= invhi;
            s[t][nt][3] *= invhi;
        }

    // ---------- phase 2: attn write + PV ----------
    float* Pbuf = Qhi;
    float* Vbuf = Khi;
    float o[4][4];
#pragma unroll
    for (int nt = 0; nt < 4; nt++)
#pragma unroll
        for (int e = 0; e < 4; e++) o[nt][e] = 0.f;

#pragma unroll
    for (int t = 0; t < 5; t++) {
        const int j0 = i0 - SPAN + t * 64;
        if (j0 < 0 || j0 >= L) continue;

        __syncthreads();
        // V^T tile (rna), permuted j layout
        {
#pragma unroll
            for (int it = 0; it < 4; it++) {
                const int c = lc0 + it * 16;
                float4 x = *(const float4*)(vTb + (size_t)lr * L + j0 + c);
                float* dv = &Vbuf[lr * ATS + (c >> 2)];
                dv[0]  = rnaf(x.x);
                dv[16] = rnaf(x.y);
                dv[32] = rnaf(x.z);
                dv[48] = rnaf(x.w);
            }
        }
        // P tile (rna) permuted + raw attn band write
#pragma unroll
        for (int nt = 0; nt < 4; nt++) {
            const int col = wn * 32 + nt * 8 + 2 * ql;
            const int jp0 = ((col) & 3) * 16 + (col >> 2);
            const int jp1 = ((col + 1) & 3) * 16 + ((col + 1) >> 2);
            Pbuf[rlo * ATS + jp0] = rnaf(s[t][nt][0]);
            Pbuf[rlo * ATS + jp1] = rnaf(s[t][nt][1]);
            Pbuf[rhi * ATS + jp0] = rnaf(s[t][nt][2]);
            Pbuf[rhi * ATS + jp1] = rnaf(s[t][nt][3]);
            if (write_attn) {
                const int jg = j0 + col;
                *(float2*)(attn_out + ((size_t)hb * L + (i0 + rlo)) * L + jg) =
                    make_float2(s[t][nt][0], s[t][nt][1]);
                *(float2*)(attn_out + ((size_t)hb * L + (i0 + rhi)) * L + jg) =
                    make_float2(s[t][nt][2], s[t][nt][3]);
            }
        }
        __syncthreads();

#pragma unroll
        for (int u = 0; u < 4; u++) {
            const int pa = rlo * ATS + ql * 16 + 4 * u;
            float4 p0 = *(const float4*)&Pbuf[pa];
            float4 p1 = *(const float4*)&Pbuf[pa + 8 * ATS];
            const int jb0 = j0 + (2 * u) * 8;
            const int jb1 = j0 + (2 * u + 1) * 8;
            const bool in0 = !((jb0 + 7 < iLo - SPAN) || (jb0 > iHi + SPAN));
            const bool in1 = !((jb1 + 7 < iLo - SPAN) || (jb1 > iHi + SPAN));
            if (!in0 && !in1) continue;
#pragma unroll
            for (int nt = 0; nt < 4; nt++) {
                const int va = (wn * 32 + nt * 8 + qr) * ATS + ql * 16 + 4 * u;
                float4 vv = *(const float4*)&Vbuf[va];
                if (in0) mma_tf32(o[nt], U(p0.x), U(p1.x), U(p0.y), U(p1.y), U(vv.x), U(vv.y));
                if (in1) mma_tf32(o[nt], U(p0.z), U(p1.z), U(p0.w), U(p1.w), U(vv.z), U(vv.w));
            }
        }
    }

    // ctx writes: [(l*B + b)*1024 + h*64 + v]
#pragma unroll
    for (int nt = 0; nt < 4; nt++) {
        const int v = wn * 32 + nt * 8 + 2 * ql;
        *(float2*)(g_ctx + ((size_t)(i0 + rlo) * Bb + b) * Dd + h * 64 + v) =
            make_float2(o[nt][0], o[nt][1]);
        *(float2*)(g_ctx + ((size_t)(i0 + rhi) * Bb + b) * Dd + h * 64 + v) =
            make_float2(o[nt][2], o[nt][3]);
    }
}

// ---------------- layernorm ----------------
__global__ __launch_bounds__(256) void ln_kernel(const float* __restrict__ yp,
                                                 const float* __restrict__ gamma,
                                                 const float* __restrict__ beta,
                                                 float* __restrict__ out)
{
    const int r = blockIdx.x;
    const int tid = threadIdx.x;
    const float* row = yp + (size_t)r * Dd;
    float v[4];
    float sum = 0.f, sq = 0.f;
#pragma unroll
    for (int u = 0; u < 4; u++) {
        v[u] = row[tid + 256 * u];
        sum += v[u];
        sq += v[u] * v[u];
    }
    __shared__ float rs[8], rq[8];
#pragma unroll
    for (int o = 16; o; o >>= 1) {
        sum += __shfl_xor_sync(~0u, sum, o);
        sq  += __shfl_xor_sync(~0u, sq, o);
    }
    if ((tid & 31) == 0) { rs[tid >> 5] = sum; rq[tid >> 5] = sq; }
    __syncthreads();
    if (tid < 32) {
        sum = (tid < 8) ? rs[tid] : 0.f;
        sq  = (tid < 8) ? rq[tid] : 0.f;
#pragma unroll
        for (int o = 4; o; o >>= 1) {
            sum += __shfl_xor_sync(~0u, sum, o);
            sq  += __shfl_xor_sync(~0u, sq, o);
        }
        if (tid == 0) {
            float mean = sum * (1.0f / Dd);
            float var = sq * (1.0f / Dd) - mean * mean;
            rs[0] = mean;
            rq[0] = rsqrtf(var + LN_EPS);
        }
    }
    __syncthreads();
    const float mean = rs[0], inv = rq[0];
#pragma unroll
    for (int u = 0; u < 4; u++) {
        const int c = tid + 256 * u;
        out[(size_t)r * Dd + c] = (v[u] - mean) * inv * gamma[c] + beta[c];
    }
}

// ---------------- launch ----------------
extern "C" void kernel_launch(void* const* d_in, const int* in_sizes, int n_in,
                              void* d_out, int out_size)
{
    const float* query = (const float*)d_in[0];
    const float* key   = (const float*)d_in[1];
    const float* value = (const float*)d_in[2];
    const float* Wq  = (const float*)d_in[3];
    const float* bq  = (const float*)d_in[4];
    const float* Wk  = (const float*)d_in[5];
    const float* bk  = (const float*)d_in[6];
    const float* Wv  = (const float*)d_in[7];
    const float* bv  = (const float*)d_in[8];
    const float* Wfc = (const float*)d_in[9];
    const float* bfc = (const float*)d_in[10];
    const float* gamma = (const float*)d_in[11];
    const float* beta  = (const float*)d_in[12];

    float* out_y = (float*)d_out;
    const int has_attn = ((size_t)out_size >= LBD + ATTN_ELEMS) ? 1 : 0;
    float* out_attn = out_y + LBD;

    float *pq, *pk, *pvT, *pctx, *pyp;
    cudaGetSymbolAddress((void**)&pq, g_q);
    cudaGetSymbolAddress((void**)&pk, g_k);
    cudaGetSymbolAddress((void**)&pvT, g_vT);
    cudaGetSymbolAddress((void**)&pctx, g_ctx);
    cudaGetSymbolAddress((void**)&pyp, g_yp);

    cudaFuncSetAttribute(mma_gemm<0>, cudaFuncAttributeMaxDynamicSharedMemorySize, GEMM_SMEM_BYTES);
    cudaFuncSetAttribute(mma_gemm<1>, cudaFuncAttributeMaxDynamicSharedMemorySize, GEMM_SMEM_BYTES);
    cudaFuncSetAttribute(mma_gemm<2>, cudaFuncAttributeMaxDynamicSharedMemorySize, GEMM_SMEM_BYTES);
    cudaFuncSetAttribute(attn_mma, cudaFuncAttributeMaxDynamicSharedMemorySize, ATTN_SMEM_BYTES);

    // overlap the big attn-zero memset with the projection GEMMs
    cudaStream_t s2 = 0;
    cudaEvent_t e1 = 0, e2 = 0;
    if (has_attn) {
        cudaStreamCreateWithFlags(&s2, cudaStreamNonBlocking);
        cudaEventCreateWithFlags(&e1, cudaEventDisableTiming);
        cudaEventCreateWithFlags(&e2, cudaEventDisableTiming);
        cudaEventRecord(e1, 0);
        cudaStreamWaitEvent(s2, e1, 0);
        cudaMemsetAsync(out_attn, 0, ATTN_ELEMS * sizeof(float), s2);
        cudaEventRecord(e2, s2);
    }

    dim3 gemm_grid(Dd / 128, MROWS / 128);  // (8, 32)
    mma_gemm<0><<<gemm_grid, 256, GEMM_SMEM_BYTES>>>(query, Wq, bq, nullptr, pq);
    mma_gemm<0><<<gemm_grid, 256, GEMM_SMEM_BYTES>>>(key,   Wk, bk, nullptr, pk);
    mma_gemm<2><<<gemm_grid, 256, GEMM_SMEM_BYTES>>>(value, Wv, bv, nullptr, pvT);

    if (has_attn) cudaStreamWaitEvent(0, e2, 0);

    dim3 attn_grid(L / 64, Bb, Hh);  // (32, 2, 16)
    attn_mma<<<attn_grid, 256, ATTN_SMEM_BYTES>>>(has_attn ? out_attn : out_y, has_attn);

    mma_gemm<1><<<gemm_grid, 256, GEMM_SMEM_BYTES>>>(pctx, Wfc, bfc, query, pyp);

    ln_kernel<<<MROWS, 256>>>(pyp, gamma, beta, out_y);
}

// round 7
// speedup vs baseline: 1.0760x; 1.0760x over previous
#include <cuda_runtime.h>
#include <math.h>
#include <stdint.h>

#define L 2048
#define Bb 2
#define Dd 1024
#define Hh 16
#define SPAN 128
#define LN_EPS 1e-5f

#define MROWS (L * Bb)                          // 4096
#define LBD ((size_t)L * Bb * Dd)               // 4,194,304
#define ATTN_ELEMS ((size_t)Hh * Bb * L * L)    // 134,217,728
#define ZF_PER_CTA 43691                        // float4 per zero-fill CTA
#define ZF_PER_LAUNCH (ZF_PER_CTA * 256)        // 11,184,896 float4

// ---------------- scratch ----------------
__device__ float g_q [Hh * Bb * L * 64];    // [h][b][l][k]  natural
__device__ float g_k [Hh * Bb * L * 64];    // [h][b][l][k]  natural
__device__ float g_vT[Hh * Bb * 64 * L];    // [h][b][v][l]  transposed
__device__ float g_ctx[MROWS * Dd];
__device__ float g_yp [MROWS * Dd];

// ---------------- helpers ----------------
__device__ __forceinline__ unsigned f2tf32(float x) {
    unsigned u;
    asm("cvt.rna.tf32.f32 %0, %1;" : "=r"(u) : "f"(x));
    return u;
}
__device__ __forceinline__ float rnaf(float x) { return __uint_as_float(f2tf32(x)); }

__device__ __forceinline__ void mma_tf32(float c[4],
                                         unsigned a0, unsigned a1, unsigned a2, unsigned a3,
                                         unsigned b0, unsigned b1) {
    asm volatile(
        "mma.sync.aligned.m16n8k8.row.col.f32.tf32.tf32.f32 "
        "{%0,%1,%2,%3},{%4,%5,%6,%7},{%8,%9},{%0,%1,%2,%3};"
        : "+f"(c[0]), "+f"(c[1]), "+f"(c[2]), "+f"(c[3])
        : "r"(a0), "r"(a1), "r"(a2), "r"(a3), "r"(b0), "r"(b1));
}

// ---------------- TF32 tensor-core GEMM (R3/R5 core): 128x128x32 tiles ----------------
// MODE 0: natural permute  out[((h*2+b)*L + l)*64 + k]   (Q, K)
// MODE 2: transposed       out[((h*2+b)*64 + k)*L + l]   (V)
// MODE 1: FC               out = acc + bias + resid
// zfill/zn: interleaved zero-fill of the attn output (projection launches only)
#define AS_STRIDE 36
#define BS_STRIDE 136
#define GEMM_BUF (128 * AS_STRIDE + 32 * BS_STRIDE)
#define GEMM_SMEM_BYTES (2 * GEMM_BUF * 4)

template <int MODE>
__global__ __launch_bounds__(256) void mma_gemm(
    const float* __restrict__ A, const float* __restrict__ B,
    const float* __restrict__ bias, const float* __restrict__ resid,
    float* __restrict__ out, float4* __restrict__ zfill, int zn)
{
    const int K = 1024, N = 1024;
    extern __shared__ float sm[];

    const int tid = threadIdx.x;
    const int lane = tid & 31;
    const int warp = tid >> 5;
    const int wm = warp >> 2;
    const int wn = warp & 3;
    const int bm = blockIdx.y * 128;
    const int bn = blockIdx.x * 128;

    const int ar = tid >> 3;
    const int ak = (tid & 7) * 4;
    const int br = tid >> 5;
    const int bc = (tid & 31) * 4;

    // zero-fill slice for this CTA
    const int zcta = blockIdx.y * gridDim.x + blockIdx.x;   // 0..255
    const long zbase = (long)zcta * ZF_PER_CTA;
    const float4 zero4 = make_float4(0.f, 0.f, 0.f, 0.f);

    float acc[4][4][4];
#pragma unroll
    for (int i = 0; i < 4; i++)
#pragma unroll
        for (int j = 0; j < 4; j++)
#pragma unroll
            for (int e = 0; e < 4; e++) acc[i][j][e] = 0.f;

    float4 pa[4], pb[4];

    auto gload = [&](int kt) {
#pragma unroll
        for (int i = 0; i < 4; i++)
            pa[i] = *(const float4*)(A + (size_t)(bm + ar + 32 * i) * K + kt * 32 + ak);
#pragma unroll
        for (int i = 0; i < 4; i++)
            pb[i] = *(const float4*)(B + (size_t)(kt * 32 + br + 8 * i) * N + bn + bc);
    };
    auto sstore = [&](int buf) {
        float* As = sm + buf * GEMM_BUF;
        float* Bs = As + 128 * AS_STRIDE;
#pragma unroll
        for (int i = 0; i < 4; i++) {
            float4 w;
            w.x = __uint_as_float(f2tf32(pa[i].x));
            w.y = __uint_as_float(f2tf32(pa[i].y));
            w.z = __uint_as_float(f2tf32(pa[i].z));
            w.w = __uint_as_float(f2tf32(pa[i].w));
            *(float4*)&As[(ar + 32 * i) * AS_STRIDE + ak] = w;
        }
#pragma unroll
        for (int i = 0; i < 4; i++) {
            float4 w;
            w.x = __uint_as_float(f2tf32(pb[i].x));
            w.y = __uint_as_float(f2tf32(pb[i].y));
            w.z = __uint_as_float(f2tf32(pb[i].z));
            w.w = __uint_as_float(f2tf32(pb[i].w));
            *(float4*)&Bs[(br + 8 * i) * BS_STRIDE + bc] = w;
        }
    };

    gload(0);
    sstore(0);
    __syncthreads();

    for (int kt = 0; kt < 32; kt++) {
        const int cur = kt & 1;
        if (kt < 31) gload(kt + 1);

        // interleaved zero-fill: 6 float4 stores per thread per kt
        if (zn > 0) {
#pragma unroll
            for (int z = 0; z < 6; z++) {
                const int lidx = (kt * 6 + z) * 256 + tid;
                const long gidx = zbase + lidx;
                if (lidx < ZF_PER_CTA && gidx < zn) zfill[gidx] = zero4;
            }
        }

        const float* As = sm + cur * GEMM_BUF;
        const float* Bs = As + 128 * AS_STRIDE;
#pragma unroll
        for (int k8 = 0; k8 < 32; k8 += 8) {
            unsigned af[4][4], bf[4][2];
#pragma unroll
            for (int mt = 0; mt < 4; mt++) {
                const int r = wm * 64 + mt * 16 + (lane >> 2);
                const int kc = k8 + (lane & 3);
                af[mt][0] = __float_as_uint(As[r * AS_STRIDE + kc]);
                af[mt][1] = __float_as_uint(As[(r + 8) * AS_STRIDE + kc]);
                af[mt][2] = __float_as_uint(As[r * AS_STRIDE + kc + 4]);
                af[mt][3] = __float_as_uint(As[(r + 8) * AS_STRIDE + kc + 4]);
            }
#pragma unroll
            for (int nt = 0; nt < 4; nt++) {
                const int cc = wn * 32 + nt * 8 + (lane >> 2);
                bf[nt][0] = __float_as_uint(Bs[(k8 + (lane & 3)) * BS_STRIDE + cc]);
                bf[nt][1] = __float_as_uint(Bs[(k8 + (lane & 3) + 4) * BS_STRIDE + cc]);
            }
#pragma unroll
            for (int mt = 0; mt < 4; mt++)
#pragma unroll
                for (int nt = 0; nt < 4; nt++)
                    mma_tf32(acc[mt][nt], af[mt][0], af[mt][1], af[mt][2], af[mt][3],
                             bf[nt][0], bf[nt][1]);
        }

        if (kt < 31) {
            sstore(1 - cur);
            __syncthreads();
        }
    }

#pragma unroll
    for (int mt = 0; mt < 4; mt++) {
#pragma unroll
        for (int nt = 0; nt < 4; nt++) {
            const int row0 = bm + wm * 64 + mt * 16 + (lane >> 2);
            const int col0 = bn + wn * 32 + nt * 8 + (lane & 3) * 2;
#pragma unroll
            for (int half = 0; half < 2; half++) {
                const int m = row0 + half * 8;
#pragma unroll
                for (int e = 0; e < 2; e++) {
                    const int n = col0 + e;
                    float val = acc[mt][nt][half * 2 + e] + bias[n];
                    if (MODE == 0) {
                        const int l = m >> 1, b = m & 1, h = n >> 6, k = n & 63;
                        out[(((size_t)(h * Bb + b) * L + l) * 64) + k] = val;
                    } else if (MODE == 2) {
                        const int l = m >> 1, b = m & 1, h = n >> 6, k = n & 63;
                        out[(((size_t)(h * Bb + b) * 64 + k) * L) + l] = val;
                    } else {
                        val += resid[(size_t)m * N + n];
                        out[(size_t)m * N + n] = val;
                    }
                }
            }
        }
    }
}

// ---------------- banded attention via mma.sync tf32 (R5 version, 146us) ----------------
#define ATS 68

__global__ __launch_bounds__(256) void attn_mma(float* __restrict__ attn_out,
                                                int write_attn)
{
    __shared__ float Abuf[64 * ATS];   // Qs (phase 1), Ps (phase 2)
    __shared__ float Bbuf[64 * ATS];   // Ks (phase 1), VTs (phase 2)
    __shared__ float Rm[2][64], Rs[2][64];

    const int tid = threadIdx.x;
    const int lane = tid & 31;
    const int wid = tid >> 5;
    const int wm = wid & 3;
    const int wn = wid >> 2;
    const int qr = lane >> 2;      // quad row
    const int ql = lane & 3;       // quad lane
    const int h = blockIdx.z;
    const int b = blockIdx.y;
    const int hb = h * Bb + b;
    const int i0 = blockIdx.x * 64;
    const int iLo = i0 + wm * 16, iHi = iLo + 15;

    const float* qb  = g_q  + (size_t)hb * L * 64;
    const float* kb  = g_k  + (size_t)hb * L * 64;
    const float* vTb = g_vT + (size_t)hb * 64 * L;

    // load Q tile natural [i][k]
    {
        const int r = tid >> 2, c0 = (tid & 3) * 4;
#pragma unroll
        for (int it = 0; it < 4; it++)
            *(float4*)&Abuf[r * ATS + c0 + it * 16] =
                *(const float4*)(qb + (size_t)(i0 + r) * 64 + c0 + it * 16);
    }

    float s[5][4][4];
#pragma unroll
    for (int t = 0; t < 5; t++)
#pragma unroll
        for (int nt = 0; nt < 4; nt++)
#pragma unroll
            for (int e = 0; e < 4; e++) s[t][nt][e] = 0.f;

    // ---------- phase 1: scores ----------
#pragma unroll
    for (int t = 0; t < 5; t++) {
        const int j0 = i0 - SPAN + t * 64;
        if (j0 < 0 || j0 >= L) continue;

        __syncthreads();
        {
            const int r = tid >> 2, c0 = (tid & 3) * 4;
#pragma unroll
            for (int it = 0; it < 4; it++)
                *(float4*)&Bbuf[r * ATS + c0 + it * 16] =
                    *(const float4*)(kb + (size_t)(j0 + r) * 64 + c0 + it * 16);
        }
        __syncthreads();

        bool ok[4];
#pragma unroll
        for (int nt = 0; nt < 4; nt++) {
            const int jlo = j0 + wn * 32 + nt * 8;
            ok[nt] = !((jlo + 7 < iLo - SPAN) || (jlo > iHi + SPAN));
        }

#pragma unroll
        for (int k8 = 0; k8 < 8; k8++) {
            const int kc = k8 * 8 + ql;
            const int ra = (wm * 16 + qr) * ATS;
            const float a0 = Abuf[ra + kc];
            const float a1 = Abuf[ra + 8 * ATS + kc];
            const float a2 = Abuf[ra + kc + 4];
            const float a3 = Abuf[ra + 8 * ATS + kc + 4];
            unsigned ah[4] = {f2tf32(a0), f2tf32(a1), f2tf32(a2), f2tf32(a3)};
            unsigned al[4] = {f2tf32(a0 - __uint_as_float(ah[0])),
                              f2tf32(a1 - __uint_as_float(ah[1])),
                              f2tf32(a2 - __uint_as_float(ah[2])),
                              f2tf32(a3 - __uint_as_float(ah[3]))};
            unsigned bh[4][2], bl[4][2];
#pragma unroll
            for (int nt = 0; nt < 4; nt++) {
                if (!ok[nt]) continue;
                const int rb = (wn * 32 + nt * 8 + qr) * ATS;
                const float b0 = Bbuf[rb + kc];
                const float b1 = Bbuf[rb + kc + 4];
                bh[nt][0] = f2tf32(b0);
                bh[nt][1] = f2tf32(b1);
                bl[nt][0] = f2tf32(b0 - __uint_as_float(bh[nt][0]));
                bl[nt][1] = f2tf32(b1 - __uint_as_float(bh[nt][1]));
            }
#pragma unroll
            for (int nt = 0; nt < 4; nt++)
                if (ok[nt]) mma_tf32(s[t][nt], ah[0], ah[1], ah[2], ah[3], bh[nt][0], bh[nt][1]);
#pragma unroll
            for (int nt = 0; nt < 4; nt++)
                if (ok[nt]) mma_tf32(s[t][nt], al[0], al[1], al[2], al[3], bh[nt][0], bh[nt][1]);
#pragma unroll
            for (int nt = 0; nt < 4; nt++)
                if (ok[nt]) mma_tf32(s[t][nt], ah[0], ah[1], ah[2], ah[3], bl[nt][0], bl[nt][1]);
        }
    }

    // scale + band mask
#pragma unroll
    for (int t = 0; t < 5; t++) {
        const int j0 = i0 - SPAN + t * 64;
#pragma unroll
        for (int nt = 0; nt < 4; nt++)
#pragma unroll
            for (int e = 0; e < 4; e++) {
                const int i = i0 + wm * 16 + qr + ((e >= 2) ? 8 : 0);
                const int j = j0 + wn * 32 + nt * 8 + 2 * ql + (e & 1);
                const int d = j - i;
                const bool valid = (j >= 0) && (j < L) && (d >= -SPAN) && (d <= SPAN);
                s[t][nt][e] = valid ? s[t][nt][e] * 0.125f : -1e30f;
            }
    }

    // ---------- softmax ----------
    const int rlo = wm * 16 + qr, rhi = rlo + 8;
    float mlo = -1e30f, mhi = -1e30f;
#pragma unroll
    for (int t = 0; t < 5; t++)
#pragma unroll
        for (int nt = 0; nt < 4; nt++) {
            mlo = fmaxf(mlo, fmaxf(s[t][nt][0], s[t][nt][1]));
            mhi = fmaxf(mhi, fmaxf(s[t][nt][2], s[t][nt][3]));
        }
    mlo = fmaxf(mlo, __shfl_xor_sync(~0u, mlo, 1));
    mlo = fmaxf(mlo, __shfl_xor_sync(~0u, mlo, 2));
    mhi = fmaxf(mhi, __shfl_xor_sync(~0u, mhi, 1));
    mhi = fmaxf(mhi, __shfl_xor_sync(~0u, mhi, 2));
    if (ql == 0) { Rm[wn][rlo] = mlo; Rm[wn][rhi] = mhi; }
    __syncthreads();
    mlo = fmaxf(Rm[0][rlo], Rm[1][rlo]);
    mhi = fmaxf(Rm[0][rhi], Rm[1][rhi]);

    float slo = 0.f, shi = 0.f;
#pragma unroll
    for (int t = 0; t < 5; t++)
#pragma unroll
        for (int nt = 0; nt < 4; nt++) {
            s[t][nt][0] = __expf(s[t][nt][0] - mlo);
            s[t][nt][1] = __expf(s[t][nt][1] - mlo);
            s[t][nt][2] = __expf(s[t][nt][2] - mhi);
            s[t][nt][3] = __expf(s[t][nt][3] - mhi);
            slo += s[t][nt][0] + s[t][nt][1];
            shi += s[t][nt][2] + s[t][nt][3];
        }
    slo += __shfl_xor_sync(~0u, slo, 1);
    slo += __shfl_xor_sync(~0u, slo, 2);
    shi += __shfl_xor_sync(~0u, shi, 1);
    shi += __shfl_xor_sync(~0u, shi, 2);
    if (ql == 0) { Rs[wn][rlo] = slo; Rs[wn][rhi] = shi; }
    __syncthreads();
    const float invlo = 1.0f / (Rs[0][rlo] + Rs[1][rlo]);
    const float invhi = 1.0f / (Rs[0][rhi] + Rs[1][rhi]);
#pragma unroll
    for (int t = 0; t < 5; t++)
#pragma unroll
        for (int nt = 0; nt < 4; nt++) {
            s[t][nt][0] *= invlo;
            s[t][nt][1] *= invlo;
            s[t][nt][2] *= invhi;
            s[t][nt][3] *= invhi;
        }

    // ---------- phase 2: attn write + PV ----------
    float o[4][4];
#pragma unroll
    for (int nt = 0; nt < 4; nt++)
#pragma unroll
        for (int e = 0; e < 4; e++) o[nt][e] = 0.f;

#pragma unroll
    for (int t = 0; t < 5; t++) {
        const int j0 = i0 - SPAN + t * 64;
        if (j0 < 0 || j0 >= L) continue;

        __syncthreads();
        // V^T tile: rows v, cols j (rna-rounded for mma)
        {
            const int r = tid >> 2, c0 = (tid & 3) * 4;
#pragma unroll
            for (int it = 0; it < 4; it++) {
                float4 x = *(const float4*)(vTb + (size_t)r * L + j0 + c0 + it * 16);
                x.x = rnaf(x.x); x.y = rnaf(x.y); x.z = rnaf(x.z); x.w = rnaf(x.w);
                *(float4*)&Bbuf[r * ATS + c0 + it * 16] = x;
            }
        }
        // P tile to smem (rna) + raw attn band write
#pragma unroll
        for (int nt = 0; nt < 4; nt++) {
            const int col = wn * 32 + nt * 8 + 2 * ql;
            Abuf[rlo * ATS + col]     = rnaf(s[t][nt][0]);
            Abuf[rlo * ATS + col + 1] = rnaf(s[t][nt][1]);
            Abuf[rhi * ATS + col]     = rnaf(s[t][nt][2]);
            Abuf[rhi * ATS + col + 1] = rnaf(s[t][nt][3]);
            if (write_attn) {
                const int jg = j0 + col;
                float2 w0 = make_float2(s[t][nt][0], s[t][nt][1]);
                float2 w1 = make_float2(s[t][nt][2], s[t][nt][3]);
                *(float2*)(attn_out + ((size_t)hb * L + (i0 + rlo)) * L + jg) = w0;
                *(float2*)(attn_out + ((size_t)hb * L + (i0 + rhi)) * L + jg) = w1;
            }
        }
        __syncthreads();

#pragma unroll
        for (int k8 = 0; k8 < 8; k8++) {
            const int jb = j0 + k8 * 8;
            if ((jb + 7 < iLo - SPAN) || (jb > iHi + SPAN)) continue;
            const int kc = k8 * 8 + ql;
            const int ra = (wm * 16 + qr) * ATS;
            const unsigned a0 = __float_as_uint(Abuf[ra + kc]);
            const unsigned a1 = __float_as_uint(Abuf[ra + 8 * ATS + kc]);
            const unsigned a2 = __float_as_uint(Abuf[ra + kc + 4]);
            const unsigned a3 = __float_as_uint(Abuf[ra + 8 * ATS + kc + 4]);
#pragma unroll
            for (int nt = 0; nt < 4; nt++) {
                const int rb = (wn * 32 + nt * 8 + qr) * ATS;
                const unsigned b0 = __float_as_uint(Bbuf[rb + kc]);
                const unsigned b1 = __float_as_uint(Bbuf[rb + kc + 4]);
                mma_tf32(o[nt], a0, a1, a2, a3, b0, b1);
            }
        }
    }

    // ctx writes: [(l*B + b)*1024 + h*64 + v]
#pragma unroll
    for (int nt = 0; nt < 4; nt++) {
        const int v = wn * 32 + nt * 8 + 2 * ql;
        *(float2*)(g_ctx + ((size_t)(i0 + rlo) * Bb + b) * Dd + h * 64 + v) =
            make_float2(o[nt][0], o[nt][1]);
        *(float2*)(g_ctx + ((size_t)(i0 + rhi) * Bb + b) * Dd + h * 64 + v) =
            make_float2(o[nt][2], o[nt][3]);
    }
}

// ---------------- layernorm ----------------
__global__ __launch_bounds__(256) void ln_kernel(const float* __restrict__ yp,
                                                 const float* __restrict__ gamma,
                                                 const float* __restrict__ beta,
                                                 float* __restrict__ out)
{
    const int r = blockIdx.x;
    const int tid = threadIdx.x;
    const float* row = yp + (size_t)r * Dd;
    float v[4];
    float sum = 0.f, sq = 0.f;
#pragma unroll
    for (int u = 0; u < 4; u++) {
        v[u] = row[tid + 256 * u];
        sum += v[u];
        sq += v[u] * v[u];
    }
    __shared__ float rs[8], rq[8];
#pragma unroll
    for (int o = 16; o; o >>= 1) {
        sum += __shfl_xor_sync(~0u, sum, o);
        sq  += __shfl_xor_sync(~0u, sq, o);
    }
    if ((tid & 31) == 0) { rs[tid >> 5] = sum; rq[tid >> 5] = sq; }
    __syncthreads();
    if (tid < 32) {
        sum = (tid < 8) ? rs[tid] : 0.f;
        sq  = (tid < 8) ? rq[tid] : 0.f;
#pragma unroll
        for (int o = 4; o; o >>= 1) {
            sum += __shfl_xor_sync(~0u, sum, o);
            sq  += __shfl_xor_sync(~0u, sq, o);
        }
        if (tid == 0) {
            float mean = sum * (1.0f / Dd);
            float var = sq * (1.0f / Dd) - mean * mean;
            rs[0] = mean;
            rq[0] = rsqrtf(var + LN_EPS);
        }
    }
    __syncthreads();
    const float mean = rs[0], inv = rq[0];
#pragma unroll
    for (int u = 0; u < 4; u++) {
        const int c = tid + 256 * u;
        out[(size_t)r * Dd + c] = (v[u] - mean) * inv * gamma[c] + beta[c];
    }
}

// ---------------- launch ----------------
extern "C" void kernel_launch(void* const* d_in, const int* in_sizes, int n_in,
                              void* d_out, int out_size)
{
    const float* query = (const float*)d_in[0];
    const float* key   = (const float*)d_in[1];
    const float* value = (const float*)d_in[2];
    const float* Wq  = (const float*)d_in[3];
    const float* bq  = (const float*)d_in[4];
    const float* Wk  = (const float*)d_in[5];
    const float* bk  = (const float*)d_in[6];
    const float* Wv  = (const float*)d_in[7];
    const float* bv  = (const float*)d_in[8];
    const float* Wfc = (const float*)d_in[9];
    const float* bfc = (const float*)d_in[10];
    const float* gamma = (const float*)d_in[11];
    const float* beta  = (const float*)d_in[12];

    float* out_y = (float*)d_out;
    const int has_attn = ((size_t)out_size >= LBD + ATTN_ELEMS) ? 1 : 0;
    float* out_attn = out_y + LBD;

    float *pq, *pk, *pvT, *pctx, *pyp;
    cudaGetSymbolAddress((void**)&pq, g_q);
    cudaGetSymbolAddress((void**)&pk, g_k);
    cudaGetSymbolAddress((void**)&pvT, g_vT);
    cudaGetSymbolAddress((void**)&pctx, g_ctx);
    cudaGetSymbolAddress((void**)&pyp, g_yp);

    cudaFuncSetAttribute(mma_gemm<0>, cudaFuncAttributeMaxDynamicSharedMemorySize, GEMM_SMEM_BYTES);
    cudaFuncSetAttribute(mma_gemm<1>, cudaFuncAttributeMaxDynamicSharedMemorySize, GEMM_SMEM_BYTES);
    cudaFuncSetAttribute(mma_gemm<2>, cudaFuncAttributeMaxDynamicSharedMemorySize, GEMM_SMEM_BYTES);

    // zero-fill slices of the attn output, fused into the 3 projection GEMMs
    const long ZTOT = (long)(ATTN_ELEMS / 4);                 // 33,554,432 float4
    float4* zp = (float4*)out_attn;
    long rem0 = has_attn ? ZTOT : 0;
    long rem1 = has_attn ? ZTOT - (long)ZF_PER_LAUNCH : 0;
    long rem2 = has_attn ? ZTOT - 2L * ZF_PER_LAUNCH : 0;
    int zn0 = (int)((rem0 > 0) ? ((rem0 > ZF_PER_LAUNCH) ? ZF_PER_LAUNCH : rem0) : 0);
    int zn1 = (int)((rem1 > 0) ? ((rem1 > ZF_PER_LAUNCH) ? ZF_PER_LAUNCH : rem1) : 0);
    int zn2 = (int)((rem2 > 0) ? ((rem2 > ZF_PER_LAUNCH) ? ZF_PER_LAUNCH : rem2) : 0);

    dim3 gemm_grid(Dd / 128, MROWS / 128);  // (8, 32)
    mma_gemm<0><<<gemm_grid, 256, GEMM_SMEM_BYTES>>>(query, Wq, bq, nullptr, pq,
                                                     zp, zn0);
    mma_gemm<0><<<gemm_grid, 256, GEMM_SMEM_BYTES>>>(key,   Wk, bk, nullptr, pk,
                                                     zp + ZF_PER_LAUNCH, zn1);
    mma_gemm<2><<<gemm_grid, 256, GEMM_SMEM_BYTES>>>(value, Wv, bv, nullptr, pvT,
                                                     zp + 2L * ZF_PER_LAUNCH, zn2);

    dim3 attn_grid(L / 64, Bb, Hh);  // (32, 2, 16)
    attn_mma<<<attn_grid, 256>>>(has_attn ? out_attn : out_y, has_attn);

    mma_gemm<1><<<gemm_grid, 256, GEMM_SMEM_BYTES>>>(pctx, Wfc, bfc, query, pyp,
                                                     zp, 0);

    ln_kernel<<<MROWS, 256>>>(pyp, gamma, beta, out_y);
}

// round 8
// speedup vs baseline: 1.1223x; 1.0430x over previous
#include <cuda_runtime.h>
#include <math.h>
#include <stdint.h>

#define L 2048
#define Bb 2
#define Dd 1024
#define Hh 16
#define SPAN 128
#define LN_EPS 1e-5f

#define MROWS (L * Bb)                          // 4096
#define LBD ((size_t)L * Bb * Dd)               // 4,194,304
#define ATTN_ELEMS ((size_t)Hh * Bb * L * L)    // 134,217,728
#define ZF_PER_CTA 43691                        // float4 per zero-fill CTA
#define ZF_PER_LAUNCH (ZF_PER_CTA * 256)        // 11,184,896 float4

// ---------------- scratch ----------------
__device__ float g_q [Hh * Bb * L * 64];    // [h][b][l][k]  natural
__device__ float g_k [Hh * Bb * L * 64];    // [h][b][l][k]  natural
__device__ float g_vT[Hh * Bb * 64 * L];    // [h][b][v][l]  transposed
__device__ float g_ctx[MROWS * Dd];
__device__ float g_yp [MROWS * Dd];

// ---------------- helpers ----------------
__device__ __forceinline__ unsigned f2tf32(float x) {
    unsigned u;
    asm("cvt.rna.tf32.f32 %0, %1;" : "=r"(u) : "f"(x));
    return u;
}
__device__ __forceinline__ float rnaf(float x) { return __uint_as_float(f2tf32(x)); }

__device__ __forceinline__ void mma_tf32(float c[4],
                                         unsigned a0, unsigned a1, unsigned a2, unsigned a3,
                                         unsigned b0, unsigned b1) {
    asm volatile(
        "mma.sync.aligned.m16n8k8.row.col.f32.tf32.tf32.f32 "
        "{%0,%1,%2,%3},{%4,%5,%6,%7},{%8,%9},{%0,%1,%2,%3};"
        : "+f"(c[0]), "+f"(c[1]), "+f"(c[2]), "+f"(c[3])
        : "r"(a0), "r"(a1), "r"(a2), "r"(a3), "r"(b0), "r"(b1));
}

// ---------------- TF32 tensor-core GEMM: 128x128x32 tiles ----------------
// MODE 0: natural permute  out[((h*2+b)*L + l)*64 + k]   (Q, K)
// MODE 2: transposed       out[((h*2+b)*64 + k)*L + l]   (V)
// MODE 1: FC               out = acc + bias + resid
// zfill/zn: interleaved zero-fill of attn output via __stcs (no L2 pollution)
#define AS_STRIDE 36
#define BS_STRIDE 136
#define GEMM_BUF (128 * AS_STRIDE + 32 * BS_STRIDE)
#define GEMM_SMEM_BYTES (2 * GEMM_BUF * 4)

template <int MODE>
__global__ __launch_bounds__(256) void mma_gemm(
    const float* __restrict__ A, const float* __restrict__ B,
    const float* __restrict__ bias, const float* __restrict__ resid,
    float* __restrict__ out, float4* __restrict__ zfill, int zn)
{
    const int K = 1024, N = 1024;
    extern __shared__ float sm[];

    const int tid = threadIdx.x;
    const int lane = tid & 31;
    const int warp = tid >> 5;
    const int wm = warp >> 2;
    const int wn = warp & 3;
    const int bm = blockIdx.y * 128;
    const int bn = blockIdx.x * 128;

    const int ar = tid >> 3;
    const int ak = (tid & 7) * 4;
    const int br = tid >> 5;
    const int bc = (tid & 31) * 4;

    const int zcta = blockIdx.y * gridDim.x + blockIdx.x;   // 0..255
    const long zbase = (long)zcta * ZF_PER_CTA;
    const float4 zero4 = make_float4(0.f, 0.f, 0.f, 0.f);

    float acc[4][4][4];
#pragma unroll
    for (int i = 0; i < 4; i++)
#pragma unroll
        for (int j = 0; j < 4; j++)
#pragma unroll
            for (int e = 0; e < 4; e++) acc[i][j][e] = 0.f;

    float4 pa[4], pb[4];

    auto gload = [&](int kt) {
#pragma unroll
        for (int i = 0; i < 4; i++)
            pa[i] = *(const float4*)(A + (size_t)(bm + ar + 32 * i) * K + kt * 32 + ak);
#pragma unroll
        for (int i = 0; i < 4; i++)
            pb[i] = *(const float4*)(B + (size_t)(kt * 32 + br + 8 * i) * N + bn + bc);
    };
    auto sstore = [&](int buf) {
        float* As = sm + buf * GEMM_BUF;
        float* Bs = As + 128 * AS_STRIDE;
#pragma unroll
        for (int i = 0; i < 4; i++) {
            float4 w;
            w.x = __uint_as_float(f2tf32(pa[i].x));
            w.y = __uint_as_float(f2tf32(pa[i].y));
            w.z = __uint_as_float(f2tf32(pa[i].z));
            w.w = __uint_as_float(f2tf32(pa[i].w));
            *(float4*)&As[(ar + 32 * i) * AS_STRIDE + ak] = w;
        }
#pragma unroll
        for (int i = 0; i < 4; i++) {
            float4 w;
            w.x = __uint_as_float(f2tf32(pb[i].x));
            w.y = __uint_as_float(f2tf32(pb[i].y));
            w.z = __uint_as_float(f2tf32(pb[i].z));
            w.w = __uint_as_float(f2tf32(pb[i].w));
            *(float4*)&Bs[(br + 8 * i) * BS_STRIDE + bc] = w;
        }
    };

    gload(0);
    sstore(0);
    __syncthreads();

    for (int kt = 0; kt < 32; kt++) {
        const int cur = kt & 1;
        if (kt < 31) gload(kt + 1);

        // interleaved zero-fill: streaming stores (evict-first; keep A/B in L2)
        if (zn > 0) {
#pragma unroll
            for (int z = 0; z < 6; z++) {
                const int lidx = (kt * 6 + z) * 256 + tid;
                const long gidx = zbase + lidx;
                if (lidx < ZF_PER_CTA && gidx < zn) __stcs(&zfill[gidx], zero4);
            }
        }

        const float* As = sm + cur * GEMM_BUF;
        const float* Bs = As + 128 * AS_STRIDE;
#pragma unroll
        for (int k8 = 0; k8 < 32; k8 += 8) {
            unsigned af[4][4], bf[4][2];
#pragma unroll
            for (int mt = 0; mt < 4; mt++) {
                const int r = wm * 64 + mt * 16 + (lane >> 2);
                const int kc = k8 + (lane & 3);
                af[mt][0] = __float_as_uint(As[r * AS_STRIDE + kc]);
                af[mt][1] = __float_as_uint(As[(r + 8) * AS_STRIDE + kc]);
                af[mt][2] = __float_as_uint(As[r * AS_STRIDE + kc + 4]);
                af[mt][3] = __float_as_uint(As[(r + 8) * AS_STRIDE + kc + 4]);
            }
#pragma unroll
            for (int nt = 0; nt < 4; nt++) {
                const int cc = wn * 32 + nt * 8 + (lane >> 2);
                bf[nt][0] = __float_as_uint(Bs[(k8 + (lane & 3)) * BS_STRIDE + cc]);
                bf[nt][1] = __float_as_uint(Bs[(k8 + (lane & 3) + 4) * BS_STRIDE + cc]);
            }
#pragma unroll
            for (int mt = 0; mt < 4; mt++)
#pragma unroll
                for (int nt = 0; nt < 4; nt++)
                    mma_tf32(acc[mt][nt], af[mt][0], af[mt][1], af[mt][2], af[mt][3],
                             bf[nt][0], bf[nt][1]);
        }

        if (kt < 31) {
            sstore(1 - cur);
            __syncthreads();
        }
    }

#pragma unroll
    for (int mt = 0; mt < 4; mt++) {
#pragma unroll
        for (int nt = 0; nt < 4; nt++) {
            const int row0 = bm + wm * 64 + mt * 16 + (lane >> 2);
            const int col0 = bn + wn * 32 + nt * 8 + (lane & 3) * 2;
#pragma unroll
            for (int half = 0; half < 2; half++) {
                const int m = row0 + half * 8;
#pragma unroll
                for (int e = 0; e < 2; e++) {
                    const int n = col0 + e;
                    float val = acc[mt][nt][half * 2 + e] + bias[n];
                    if (MODE == 0) {
                        const int l = m >> 1, b = m & 1, h = n >> 6, k = n & 63;
                        out[(((size_t)(h * Bb + b) * L + l) * 64) + k] = val;
                    } else if (MODE == 2) {
                        const int l = m >> 1, b = m & 1, h = n >> 6, k = n & 63;
                        out[(((size_t)(h * Bb + b) * 64 + k) * L) + l] = val;
                    } else {
                        val += resid[(size_t)m * N + n];
                        out[(size_t)m * N + n] = val;
                    }
                }
            }
        }
    }
}

// ---------------- banded attention: mma.sync tf32, split hoisted, R5 layout ----------------
// 4 smem tiles (stride 68, scalar frag loads = conflict-free): Qhi,Qlo,Khi,Klo.
// Phase 2 reuses Qhi as P, Khi as V^T.
#define ATS 68
#define ATTN_SMEM_BYTES (4 * 64 * ATS * 4)

__global__ __launch_bounds__(256, 2) void attn_mma(float* __restrict__ attn_out,
                                                   int write_attn)
{
    extern __shared__ float sbuf[];
    float* Qhi = sbuf;                 // phase2: P
    float* Qlo = sbuf + 64 * ATS;
    float* Khi = sbuf + 2 * 64 * ATS;  // phase2: V^T
    float* Klo = sbuf + 3 * 64 * ATS;
    __shared__ float Rm[2][64], Rs[2][64];

    const int tid = threadIdx.x;
    const int lane = tid & 31;
    const int wid = tid >> 5;
    const int wm = wid & 3;
    const int wn = wid >> 2;
    const int qr = lane >> 2;
    const int ql = lane & 3;
    const int h = blockIdx.z;
    const int b = blockIdx.y;
    const int hb = h * Bb + b;
    const int i0 = blockIdx.x * 64;
    const int iLo = i0 + wm * 16, iHi = iLo + 15;

    const float* qb  = g_q  + (size_t)hb * L * 64;
    const float* kb  = g_k  + (size_t)hb * L * 64;
    const float* vTb = g_vT + (size_t)hb * 64 * L;

    const int lr = tid >> 2;           // loader row 0..63
    const int lc0 = (tid & 3) * 4;     // loader col base

    // load Q tile, split hi/lo once
    {
#pragma unroll
        for (int it = 0; it < 4; it++) {
            const int c = lc0 + it * 16;
            float4 x = *(const float4*)(qb + (size_t)(i0 + lr) * 64 + c);
            float4 hi, lo;
            hi.x = rnaf(x.x); lo.x = rnaf(x.x - hi.x);
            hi.y = rnaf(x.y); lo.y = rnaf(x.y - hi.y);
            hi.z = rnaf(x.z); lo.z = rnaf(x.z - hi.z);
            hi.w = rnaf(x.w); lo.w = rnaf(x.w - hi.w);
            *(float4*)&Qhi[lr * ATS + c] = hi;
            *(float4*)&Qlo[lr * ATS + c] = lo;
        }
    }

    float s[5][4][4];
#pragma unroll
    for (int t = 0; t < 5; t++)
#pragma unroll
        for (int nt = 0; nt < 4; nt++)
#pragma unroll
            for (int e = 0; e < 4; e++) s[t][nt][e] = 0.f;

    // ---------- phase 1: scores ----------
#pragma unroll
    for (int t = 0; t < 5; t++) {
        const int j0 = i0 - SPAN + t * 64;
        if (j0 < 0 || j0 >= L) continue;

        __syncthreads();
        {
#pragma unroll
            for (int it = 0; it < 4; it++) {
                const int c = lc0 + it * 16;
                float4 x = *(const float4*)(kb + (size_t)(j0 + lr) * 64 + c);
                float4 hi, lo;
                hi.x = rnaf(x.x); lo.x = rnaf(x.x - hi.x);
                hi.y = rnaf(x.y); lo.y = rnaf(x.y - hi.y);
                hi.z = rnaf(x.z); lo.z = rnaf(x.z - hi.z);
                hi.w = rnaf(x.w); lo.w = rnaf(x.w - hi.w);
                *(float4*)&Khi[lr * ATS + c] = hi;
                *(float4*)&Klo[lr * ATS + c] = lo;
            }
        }
        __syncthreads();

        bool ok[4];
#pragma unroll
        for (int nt = 0; nt < 4; nt++) {
            const int jlo = j0 + wn * 32 + nt * 8;
            ok[nt] = !((jlo + 7 < iLo - SPAN) || (jlo > iHi + SPAN));
        }

#pragma unroll
        for (int k8 = 0; k8 < 8; k8++) {
            const int kc = k8 * 8 + ql;
            const int ra = (wm * 16 + qr) * ATS;
            const unsigned ah0 = __float_as_uint(Qhi[ra + kc]);
            const unsigned ah1 = __float_as_uint(Qhi[ra + 8 * ATS + kc]);
            const unsigned ah2 = __float_as_uint(Qhi[ra + kc + 4]);
            const unsigned ah3 = __float_as_uint(Qhi[ra + 8 * ATS + kc + 4]);
            const unsigned al0 = __float_as_uint(Qlo[ra + kc]);
            const unsigned al1 = __float_as_uint(Qlo[ra + 8 * ATS + kc]);
            const unsigned al2 = __float_as_uint(Qlo[ra + kc + 4]);
            const unsigned al3 = __float_as_uint(Qlo[ra + 8 * ATS + kc + 4]);
#pragma unroll
            for (int nt = 0; nt < 4; nt++) {
                if (!ok[nt]) continue;
                const int rb = (wn * 32 + nt * 8 + qr) * ATS;
                const unsigned bh0 = __float_as_uint(Khi[rb + kc]);
                const unsigned bh1 = __float_as_uint(Khi[rb + kc + 4]);
                const unsigned bl0 = __float_as_uint(Klo[rb + kc]);
                const unsigned bl1 = __float_as_uint(Klo[rb + kc + 4]);
                mma_tf32(s[t][nt], ah0, ah1, ah2, ah3, bh0, bh1);
                mma_tf32(s[t][nt], al0, al1, al2, al3, bh0, bh1);
                mma_tf32(s[t][nt], ah0, ah1, ah2, ah3, bl0, bl1);
            }
        }
    }

    // scale + band mask
#pragma unroll
    for (int t = 0; t < 5; t++) {
        const int j0 = i0 - SPAN + t * 64;
#pragma unroll
        for (int nt = 0; nt < 4; nt++)
#pragma unroll
            for (int e = 0; e < 4; e++) {
                const int i = i0 + wm * 16 + qr + ((e >= 2) ? 8 : 0);
                const int j = j0 + wn * 32 + nt * 8 + 2 * ql + (e & 1);
                const int d = j - i;
                const bool valid = (j >= 0) && (j < L) && (d >= -SPAN) && (d <= SPAN);
                s[t][nt][e] = valid ? s[t][nt][e] * 0.125f : -1e30f;
            }
    }

    // ---------- softmax ----------
    const int rlo = wm * 16 + qr, rhi = rlo + 8;
    float mlo = -1e30f, mhi = -1e30f;
#pragma unroll
    for (int t = 0; t < 5; t++)
#pragma unroll
        for (int nt = 0; nt < 4; nt++) {
            mlo = fmaxf(mlo, fmaxf(s[t][nt][0], s[t][nt][1]));
            mhi = fmaxf(mhi, fmaxf(s[t][nt][2], s[t][nt][3]));
        }
    mlo = fmaxf(mlo, __shfl_xor_sync(~0u, mlo, 1));
    mlo = fmaxf(mlo, __shfl_xor_sync(~0u, mlo, 2));
    mhi = fmaxf(mhi, __shfl_xor_sync(~0u, mhi, 1));
    mhi = fmaxf(mhi, __shfl_xor_sync(~0u, mhi, 2));
    if (ql == 0) { Rm[wn][rlo] = mlo; Rm[wn][rhi] = mhi; }
    __syncthreads();
    mlo = fmaxf(Rm[0][rlo], Rm[1][rlo]);
    mhi = fmaxf(Rm[0][rhi], Rm[1][rhi]);

    float slo = 0.f, shi = 0.f;
#pragma unroll
    for (int t = 0; t < 5; t++)
#pragma unroll
        for (int nt = 0; nt < 4; nt++) {
            s[t][nt][0] = __expf(s[t][nt][0] - mlo);
            s[t][nt][1] = __expf(s[t][nt][1] - mlo);
            s[t][nt][2] = __expf(s[t][nt][2] - mhi);
            s[t][nt][3] = __expf(s[t][nt][3] - mhi);
            slo += s[t][nt][0] + s[t][nt][1];
            shi += s[t][nt][2] + s[t][nt][3];
        }
    slo += __shfl_xor_sync(~0u, slo, 1);
    slo += __shfl_xor_sync(~0u, slo, 2);
    shi += __shfl_xor_sync(~0u, shi, 1);
    shi += __shfl_xor_sync(~0u, shi, 2);
    if (ql == 0) { Rs[wn][rlo] = slo; Rs[wn][rhi] = shi; }
    __syncthreads();
    const float invlo = 1.0f / (Rs[0][rlo] + Rs[1][rlo]);
    const float invhi = 1.0f / (Rs[0][rhi] + Rs[1][rhi]);
#pragma unroll
    for (int t = 0; t < 5; t++)
#pragma unroll
        for (int nt = 0; nt < 4; nt++) {
            s[t][nt][0] *= invlo;
            s[t][nt][1] *= invlo;
            s[t][nt][2] *= invhi;
            s[t][nt][3] *= invhi;
        }

    // ---------- phase 2: attn write + PV ----------
    float* Pbuf = Qhi;
    float* Vbuf = Khi;
    float o[4][4];
#pragma unroll
    for (int nt = 0; nt < 4; nt++)
#pragma unroll
        for (int e = 0; e < 4; e++) o[nt][e] = 0.f;

#pragma unroll
    for (int t = 0; t < 5; t++) {
        const int j0 = i0 - SPAN + t * 64;
        if (j0 < 0 || j0 >= L) continue;

        __syncthreads();
        // V^T tile: rows v, cols j (rna-rounded)
        {
#pragma unroll
            for (int it = 0; it < 4; it++) {
                const int c = lc0 + it * 16;
                float4 x = *(const float4*)(vTb + (size_t)lr * L + j0 + c);
                x.x = rnaf(x.x); x.y = rnaf(x.y); x.z = rnaf(x.z); x.w = rnaf(x.w);
                *(float4*)&Vbuf[lr * ATS + c] = x;
            }
        }
        // P tile to smem (rna) + raw attn band write
#pragma unroll
        for (int nt = 0; nt < 4; nt++) {
            const int col = wn * 32 + nt * 8 + 2 * ql;
            Pbuf[rlo * ATS + col]     = rnaf(s[t][nt][0]);
            Pbuf[rlo * ATS + col + 1] = rnaf(s[t][nt][1]);
            Pbuf[rhi * ATS + col]     = rnaf(s[t][nt][2]);
            Pbuf[rhi * ATS + col + 1] = rnaf(s[t][nt][3]);
            if (write_attn) {
                const int jg = j0 + col;
                *(float2*)(attn_out + ((size_t)hb * L + (i0 + rlo)) * L + jg) =
                    make_float2(s[t][nt][0], s[t][nt][1]);
                *(float2*)(attn_out + ((size_t)hb * L + (i0 + rhi)) * L + jg) =
                    make_float2(s[t][nt][2], s[t][nt][3]);
            }
        }
        __syncthreads();

#pragma unroll
        for (int k8 = 0; k8 < 8; k8++) {
            const int jb = j0 + k8 * 8;
            if ((jb + 7 < iLo - SPAN) || (jb > iHi + SPAN)) continue;
            const int kc = k8 * 8 + ql;
            const int ra = (wm * 16 + qr) * ATS;
            const unsigned a0 = __float_as_uint(Pbuf[ra + kc]);
            const unsigned a1 = __float_as_uint(Pbuf[ra + 8 * ATS + kc]);
            const unsigned a2 = __float_as_uint(Pbuf[ra + kc + 4]);
            const unsigned a3 = __float_as_uint(Pbuf[ra + 8 * ATS + kc + 4]);
#pragma unroll
            for (int nt = 0; nt < 4; nt++) {
                const int rb = (wn * 32 + nt * 8 + qr) * ATS;
                const unsigned b0 = __float_as_uint(Vbuf[rb + kc]);
                const unsigned b1 = __float_as_uint(Vbuf[rb + kc + 4]);
                mma_tf32(o[nt], a0, a1, a2, a3, b0, b1);
            }
        }
    }

    // ctx writes
#pragma unroll
    for (int nt = 0; nt < 4; nt++) {
        const int v = wn * 32 + nt * 8 + 2 * ql;
        *(float2*)(g_ctx + ((size_t)(i0 + rlo) * Bb + b) * Dd + h * 64 + v) =
            make_float2(o[nt][0], o[nt][1]);
        *(float2*)(g_ctx + ((size_t)(i0 + rhi) * Bb + b) * Dd + h * 64 + v) =
            make_float2(o[nt][2], o[nt][3]);
    }
}

// ---------------- layernorm ----------------
__global__ __launch_bounds__(256) void ln_kernel(const float* __restrict__ yp,
                                                 const float* __restrict__ gamma,
                                                 const float* __restrict__ beta,
                                                 float* __restrict__ out)
{
    const int r = blockIdx.x;
    const int tid = threadIdx.x;
    const float* row = yp + (size_t)r * Dd;
    float v[4];
    float sum = 0.f, sq = 0.f;
#pragma unroll
    for (int u = 0; u < 4; u++) {
        v[u] = row[tid + 256 * u];
        sum += v[u];
        sq += v[u] * v[u];
    }
    __shared__ float rs[8], rq[8];
#pragma unroll
    for (int o = 16; o; o >>= 1) {
        sum += __shfl_xor_sync(~0u, sum, o);
        sq  += __shfl_xor_sync(~0u, sq, o);
    }
    if ((tid & 31) == 0) { rs[tid >> 5] = sum; rq[tid >> 5] = sq; }
    __syncthreads();
    if (tid < 32) {
        sum = (tid < 8) ? rs[tid] : 0.f;
        sq  = (tid < 8) ? rq[tid] : 0.f;
#pragma unroll
        for (int o = 4; o; o >>= 1) {
            sum += __shfl_xor_sync(~0u, sum, o);
            sq  += __shfl_xor_sync(~0u, sq, o);
        }
        if (tid == 0) {
            float mean = sum * (1.0f / Dd);
            float var = sq * (1.0f / Dd) - mean * mean;
            rs[0] = mean;
            rq[0] = rsqrtf(var + LN_EPS);
        }
    }
    __syncthreads();
    const float mean = rs[0], inv = rq[0];
#pragma unroll
    for (int u = 0; u < 4; u++) {
        const int c = tid + 256 * u;
        out[(size_t)r * Dd + c] = (v[u] - mean) * inv * gamma[c] + beta[c];
    }
}

// ---------------- launch ----------------
extern "C" void kernel_launch(void* const* d_in, const int* in_sizes, int n_in,
                              void* d_out, int out_size)
{
    const float* query = (const float*)d_in[0];
    const float* key   = (const float*)d_in[1];
    const float* value = (const float*)d_in[2];
    const float* Wq  = (const float*)d_in[3];
    const float* bq  = (const float*)d_in[4];
    const float* Wk  = (const float*)d_in[5];
    const float* bk  = (const float*)d_in[6];
    const float* Wv  = (const float*)d_in[7];
    const float* bv  = (const float*)d_in[8];
    const float* Wfc = (const float*)d_in[9];
    const float* bfc = (const float*)d_in[10];
    const float* gamma = (const float*)d_in[11];
    const float* beta  = (const float*)d_in[12];

    float* out_y = (float*)d_out;
    const int has_attn = ((size_t)out_size >= LBD + ATTN_ELEMS) ? 1 : 0;
    float* out_attn = out_y + LBD;

    float *pq, *pk, *pvT, *pctx, *pyp;
    cudaGetSymbolAddress((void**)&pq, g_q);
    cudaGetSymbolAddress((void**)&pk, g_k);
    cudaGetSymbolAddress((void**)&pvT, g_vT);
    cudaGetSymbolAddress((void**)&pctx, g_ctx);
    cudaGetSymbolAddress((void**)&pyp, g_yp);

    cudaFuncSetAttribute(mma_gemm<0>, cudaFuncAttributeMaxDynamicSharedMemorySize, GEMM_SMEM_BYTES);
    cudaFuncSetAttribute(mma_gemm<1>, cudaFuncAttributeMaxDynamicSharedMemorySize, GEMM_SMEM_BYTES);
    cudaFuncSetAttribute(mma_gemm<2>, cudaFuncAttributeMaxDynamicSharedMemorySize, GEMM_SMEM_BYTES);
    cudaFuncSetAttribute(attn_mma, cudaFuncAttributeMaxDynamicSharedMemorySize, ATTN_SMEM_BYTES);

    // zero-fill slices of the attn output, fused into the 3 projection GEMMs
    const long ZTOT = (long)(ATTN_ELEMS / 4);                 // 33,554,432 float4
    float4* zp = (float4*)out_attn;
    long rem0 = has_attn ? ZTOT : 0;
    long rem1 = has_attn ? ZTOT - (long)ZF_PER_LAUNCH : 0;
    long rem2 = has_attn ? ZTOT - 2L * ZF_PER_LAUNCH : 0;
    int zn0 = (int)((rem0 > 0) ? ((rem0 > ZF_PER_LAUNCH) ? ZF_PER_LAUNCH : rem0) : 0);
    int zn1 = (int)((rem1 > 0) ? ((rem1 > ZF_PER_LAUNCH) ? ZF_PER_LAUNCH : rem1) : 0);
    int zn2 = (int)((rem2 > 0) ? ((rem2 > ZF_PER_LAUNCH) ? ZF_PER_LAUNCH : rem2) : 0);

    dim3 gemm_grid(Dd / 128, MROWS / 128);  // (8, 32)
    mma_gemm<0><<<gemm_grid, 256, GEMM_SMEM_BYTES>>>(query, Wq, bq, nullptr, pq,
                                                     zp, zn0);
    mma_gemm<0><<<gemm_grid, 256, GEMM_SMEM_BYTES>>>(key,   Wk, bk, nullptr, pk,
                                                     zp + ZF_PER_LAUNCH, zn1);
    mma_gemm<2><<<gemm_grid, 256, GEMM_SMEM_BYTES>>>(value, Wv, bv, nullptr, pvT,
                                                     zp + 2L * ZF_PER_LAUNCH, zn2);

    dim3 attn_grid(L / 64, Bb, Hh);  // (32, 2, 16)
    attn_mma<<<attn_grid, 256, ATTN_SMEM_BYTES>>>(has_attn ? out_attn : out_y, has_attn);

    mma_gemm<1><<<gemm_grid, 256, GEMM_SMEM_BYTES>>>(pctx, Wfc, bfc, query, pyp,
                                                     zp, 0);

    ln_kernel<<<MROWS, 256>>>(pyp, gamma, beta, out_y);
}